// round 6
// baseline (speedup 1.0000x reference)
#include <cuda_runtime.h>
#include <math.h>

// Problem constants (fixed shapes)
#define B_   4
#define C_   64
#define H_   282
#define W_   282
#define P_   12000
#define HW_  (H_ * W_)        // 79524
#define NQ_  (HW_ / 4)        // 19881 float4-quads per channel image
#define QB_  32               // quads per gather block
#define QBLK_ ((NQ_ + QB_ - 1) / QB_)   // 622 quad-blocks per batch
#define SLOTS_ (4 * QB_)      // 128 winner slots per block

#define PT_  (P_ / 32)        // 375 pillar tiles (exact)
#define CT_  (C_ / 32)        // 2  channel tiles
#define TRANS_BLOCKS_ (B_ * PT_ * CT_)            // 3000
#define IDX_BLOCKS_   ((B_ * P_ + 255) / 256)     // 188

// Scratch (device globals; zero-initialized at load; g_winner self-resets)
__device__ __align__(16) int   g_winner[B_ * HW_];     // (p+1) of winning pillar, 0 = empty
__device__ __align__(16) float g_tf[B_ * P_ * C_];     // feats transposed to (B, P, C)

// ---------------------------------------------------------------------------
// Kernel 1 (fused): blocks [0, 3000) transpose feats (B,C,P) -> g_tf (B,P,C)
// via 32x32 smem tiles; blocks [3000, 3188) compute per-pillar cells and
// atomicMax(p+1) into g_winner (sequential last-update-wins == max p).
// Index math matches XLA fast-math lowering: (x + 22) * 6.25f (bit-verified).
// ---------------------------------------------------------------------------
__global__ void k_prep(const float* __restrict__ feats,
                       const float* __restrict__ pin) {
    if (blockIdx.x < TRANS_BLOCKS_) {
        __shared__ float tile[32][33];
        int bid   = blockIdx.x;
        int b     = bid / (PT_ * CT_);
        int rem   = bid - b * (PT_ * CT_);
        int ctile = rem / PT_;
        int ptile = rem - ctile * PT_;
        int tx = threadIdx.x & 31;
        int ty = threadIdx.x >> 5;

        const float* src = feats + ((size_t)b * C_ + ctile * 32) * P_ + ptile * 32;
        #pragma unroll
        for (int i = 0; i < 4; i++) {
            int cl = ty + 8 * i;
            tile[cl][tx] = src[(size_t)cl * P_ + tx];
        }
        __syncthreads();
        float* dst = g_tf + ((size_t)b * P_ + ptile * 32) * C_ + ctile * 32;
        #pragma unroll
        for (int i = 0; i < 4; i++) {
            int pl = ty + 8 * i;
            dst[(size_t)pl * C_ + tx] = tile[tx][pl];
        }
    } else {
        int i = (blockIdx.x - TRANS_BLOCKS_) * 256 + threadIdx.x;
        if (i >= B_ * P_) return;
        int b = i / P_;
        int p = i - b * P_;

        float x = pin[(b * 2 + 0) * P_ + p];
        if (x == 0.0f) return;            // invalid pillars dropped (OOB in ref)
        float y = pin[(b * 2 + 1) * P_ + p];

        int xg = (int)floorf(__fmul_rn(__fadd_rn(x, 22.0f), 6.25f));
        int yg = (int)floorf(__fmul_rn(__fadd_rn(y, 22.0f), 6.25f));
        xg = min(max(xg, 0), W_ - 1);
        yg = min(max(yg, 0), H_ - 1);
        atomicMax(&g_winner[b * HW_ + yg * W_ + xg], p + 1);
    }
}

// ---------------------------------------------------------------------------
// Kernel 2: GATHER with smem staging. Block = (b, 32 quads), 256 threads.
//  S1: warp 0 loads the 32 winner int4s -> smem, self-resets them (zero-fills
//      slots beyond the tail block's nq).
//  S2: filled pillars (~14%) are staged cooperatively: one HALF-WARP loads one
//      pillar's contiguous 256B transposed-feature block (coalesced, 2 lines)
//      into smem, swizzled as feat_s[s*64 + (c ^ (s>>2))].
//  S3: thread (q=lane, cg=warp) emits 8 dense coalesced float4 stores; its
//      smem reads hit bank (c ^ q) & 31 -> conflict-free across the warp.
// The store stream now has NO global-load dependence (k_zero-like behavior).
// ---------------------------------------------------------------------------
__global__ void __launch_bounds__(256) k_gather(float4* __restrict__ out) {
    __shared__ int   w_flat[SLOTS_];
    __shared__ float feat_s[SLOTS_ * 64];

    int blk   = blockIdx.x;
    int b     = blk / QBLK_;
    int qblk  = blk - b * QBLK_;
    int qbase = qblk * QB_;
    int nq    = min(QB_, NQ_ - qbase);     // last block per batch: 9

    int tid  = threadIdx.x;
    int lane = tid & 31;
    int warp = tid >> 5;

    // ---- S1: winners -> smem, self-reset globals ----
    int4* w4 = (int4*)g_winner;
    if (tid < 32) {
        int4 w = make_int4(0, 0, 0, 0);
        if (tid < nq) {
            int gi = b * NQ_ + qbase + tid;
            w = w4[gi];
            w4[gi] = make_int4(0, 0, 0, 0);
        }
        *(int4*)&w_flat[4 * tid] = w;
    }
    __syncthreads();

    // ---- S2: stage filled pillars (half-warp per slot, 2 slots/warp/iter) ----
    const float* tb = g_tf + (size_t)b * P_ * C_;
    int half = lane >> 4;        // 0/1: which of the two slots this iter
    int hl   = lane & 15;        // float4 chunk within the 256B block
    #pragma unroll
    for (int it = 0; it < 8; it++) {
        int s = warp * 16 + it * 2 + half;      // slot 0..127
        int w = w_flat[s];                      // broadcast within half-warp
        if (w > 0) {
            float4 v = __ldg((const float4*)(tb + (size_t)(w - 1) * C_) + hl);
            int q  = s >> 2;
            float* fs = feat_s + s * 64;
            int c0 = 4 * hl;
            fs[(c0 + 0) ^ q] = v.x;
            fs[(c0 + 1) ^ q] = v.y;
            fs[(c0 + 2) ^ q] = v.z;
            fs[(c0 + 3) ^ q] = v.w;
        }
    }
    __syncthreads();

    // ---- S3: dense coalesced store bursts ----
    int q  = lane;
    int cg = warp;               // channel group of 8
    if (q >= nq) return;

    int4 w = *(const int4*)&w_flat[4 * q];
    const float* f0 = feat_s + (4 * q + 0) * 64;
    const float* f1 = feat_s + (4 * q + 1) * 64;
    const float* f2 = feat_s + (4 * q + 2) * 64;
    const float* f3 = feat_s + (4 * q + 3) * 64;

    float4* ob = out + ((size_t)b * C_ + cg * 8) * NQ_ + qbase + q;
    #pragma unroll
    for (int k = 0; k < 8; k++) {
        int ci = (cg * 8 + k) ^ q;            // conflict-free bank = (c^q)&31
        float4 v;
        v.x = (w.x > 0) ? f0[ci] : 0.0f;
        v.y = (w.y > 0) ? f1[ci] : 0.0f;
        v.z = (w.z > 0) ? f2[ci] : 0.0f;
        v.w = (w.w > 0) ? f3[ci] : 0.0f;
        ob[(size_t)k * NQ_] = v;
    }
}

// ---------------------------------------------------------------------------
extern "C" void kernel_launch(void* const* d_in, const int* in_sizes, int n_in,
                              void* d_out, int out_size) {
    const float* pfn_input  = (const float*)d_in[0];   // (4, 2, 12000, 1)
    const float* pfn_output = (const float*)d_in[1];   // (4, 64, 12000)
    float* out = (float*)d_out;                        // (4, 64, 282, 282)

    k_prep  <<<TRANS_BLOCKS_ + IDX_BLOCKS_, 256>>>(pfn_output, pfn_input);
    k_gather<<<B_ * QBLK_,                  256>>>((float4*)out);
}